// round 6
// baseline (speedup 1.0000x reference)
#include <cuda_runtime.h>
#include <cuda_bf16.h>
#include <math.h>

#define RES    2048
#define EMBED  256
#define TLEN   512
#define BATCH  4
#define NTOK   (BATCH*TLEN)
#define SQV    225
#define NHEAD2 450
#define VOCAB  50257
#define NCTA_REC 128
#define ROWS_REC 16

static const size_t LOGITS_N = (size_t)NTOK * VOCAB;

__device__ float    g_Wc[RES * EMBED];
__device__ float    g_xin[(size_t)NTOK * RES];
__device__ float    g_states_bt[(size_t)NTOK * RES];
__device__ float    g_L[(size_t)NTOK * NHEAD2];
__device__ float    g_Whcat[NHEAD2 * RES];
__device__ float    g_h[2][NCTA_REC][64];     // double-buffered h chunks [b*16+kloc]
__device__ unsigned g_flag[NCTA_REC];         // last step produced by each CTA
__device__ float    g_loss_acc;
__device__ int      g_mask_cnt;

__device__ __forceinline__ unsigned ld_acq(const unsigned* p) {
    unsigned v;
    asm volatile("ld.acquire.gpu.u32 %0, [%1];" : "=r"(v) : "l"(p) : "memory");
    return v;
}
__device__ __forceinline__ void st_rel(unsigned* p, unsigned v) {
    asm volatile("st.release.gpu.u32 [%0], %1;" :: "l"(p), "r"(v) : "memory");
}
__device__ __forceinline__ ulonglong2 ldcg_u2(const ulonglong2* p) {
    ulonglong2 v;
    asm volatile("ld.global.cg.v2.u64 {%0,%1}, [%2];" : "=l"(v.x), "=l"(v.y) : "l"(p));
    return v;
}
// packed dual-FMA: d(f32x2) += a(f32x2) * b(f32x2)
__device__ __forceinline__ void ffma2(unsigned long long& d,
                                      unsigned long long a,
                                      unsigned long long b) {
    asm("fma.rn.f32x2 %0, %1, %2, %0;" : "+l"(d) : "l"(a), "l"(b));
}

__global__ void prep_kernel(const float* __restrict__ Wh1, const float* __restrict__ Wh2) {
    int i0 = blockIdx.x * blockDim.x + threadIdx.x;
    int stride = gridDim.x * blockDim.x;
    for (int j = i0; j < NHEAD2 * RES; j += stride) {
        int v = j / RES, r = j - v * RES;
        g_Whcat[j] = (v < SQV) ? Wh1[v * RES + r] : Wh2[(v - SQV) * RES + r];
    }
    if (i0 < NCTA_REC) g_flag[i0] = 0u;
    if (i0 == 0) { g_loss_acc = 0.f; g_mask_cnt = 0; }
}

// Wc = W_ih[2048x2048] @ W_in[2048x256]   (NN GEMM)
__global__ __launch_bounds__(256) void gemm_nn_wc(const float* __restrict__ A,
                                                  const float* __restrict__ B) {
    const int N = EMBED, K = RES;
    __shared__ float As[16][68];
    __shared__ float Bs[16][68];
    int m0 = blockIdx.x * 64, n0 = blockIdx.y * 64;
    int tid = threadIdx.x;
    int lr = tid >> 2, lk = tid & 3;
    const float* Arow = A + (size_t)(m0 + lr) * K + lk * 4;
    int bk = tid >> 4, bn = tid & 15;
    const float* Bpos = B + (size_t)bk * N + n0 + bn * 4;
    int tx = tid & 15, ty = tid >> 4;
    float acc[4][4] = {};
    float4 av = *(const float4*)(Arow);
    float4 bv = *(const float4*)(Bpos);
    for (int k0 = 0; k0 < K; k0 += 16) {
        As[lk*4+0][lr]=av.x; As[lk*4+1][lr]=av.y; As[lk*4+2][lr]=av.z; As[lk*4+3][lr]=av.w;
        *(float4*)&Bs[bk][bn*4] = bv;
        __syncthreads();
        if (k0 + 16 < K) {
            av = *(const float4*)(Arow + k0 + 16);
            bv = *(const float4*)(Bpos + (size_t)(k0 + 16) * N);
        }
        #pragma unroll
        for (int kk = 0; kk < 16; kk++) {
            float4 a4 = *(const float4*)&As[kk][ty*4];
            float4 b4 = *(const float4*)&Bs[kk][tx*4];
            float a_[4]={a4.x,a4.y,a4.z,a4.w}, b_[4]={b4.x,b4.y,b4.z,b4.w};
            #pragma unroll
            for (int i=0;i<4;i++)
                #pragma unroll
                for (int j=0;j<4;j++) acc[i][j] += a_[i]*b_[j];
        }
        __syncthreads();
    }
    #pragma unroll
    for (int i=0;i<4;i++) {
        int m = m0 + ty*4 + i;
        #pragma unroll
        for (int j=0;j<4;j++) g_Wc[(size_t)m*N + n0 + tx*4 + j] = acc[i][j];
    }
}

// NT GEMM. mode 0: g_xin = wte[idx] @ Wc^T + b_ih + b_hh   (M=2048,N=2048,K=256)
//          mode 1: g_L   = g_states_bt @ g_Whcat^T          (M=2048,N=450, K=2048)
__global__ __launch_bounds__(256) void gemm_nt(int mode, const float* __restrict__ Aext,
                                               const int* __restrict__ gather,
                                               const float* __restrict__ bias1,
                                               const float* __restrict__ bias2,
                                               int N, int K) {
    const float *A, *B; float* C;
    if (mode == 0) { A = Aext;        B = g_Wc;    C = g_xin; }
    else           { A = g_states_bt; B = g_Whcat; C = g_L;   }
    __shared__ float As[16][68];
    __shared__ float Bs[16][68];
    int m0 = blockIdx.x * 64, n0 = blockIdx.y * 64;
    int tid = threadIdx.x;
    int lr = tid >> 2, lk = tid & 3;
    int am = m0 + lr;
    int arow = gather ? gather[am] : am;
    const float* Arow = A + (size_t)arow * K + lk * 4;
    int bn = n0 + lr;
    bool bvalid = (bn < N);
    const float* Brow = B + (size_t)(bvalid ? bn : 0) * K + lk * 4;
    int tx = tid & 15, ty = tid >> 4;
    float acc[4][4] = {};
    float4 av = *(const float4*)(Arow);
    float4 bv = bvalid ? *(const float4*)(Brow) : make_float4(0,0,0,0);
    for (int k0 = 0; k0 < K; k0 += 16) {
        As[lk*4+0][lr]=av.x; As[lk*4+1][lr]=av.y; As[lk*4+2][lr]=av.z; As[lk*4+3][lr]=av.w;
        Bs[lk*4+0][lr]=bv.x; Bs[lk*4+1][lr]=bv.y; Bs[lk*4+2][lr]=bv.z; Bs[lk*4+3][lr]=bv.w;
        __syncthreads();
        if (k0 + 16 < K) {
            av = *(const float4*)(Arow + k0 + 16);
            bv = bvalid ? *(const float4*)(Brow + k0 + 16) : make_float4(0,0,0,0);
        }
        #pragma unroll
        for (int kk = 0; kk < 16; kk++) {
            float4 a4 = *(const float4*)&As[kk][ty*4];
            float4 b4 = *(const float4*)&Bs[kk][tx*4];
            float a_[4]={a4.x,a4.y,a4.z,a4.w}, b_[4]={b4.x,b4.y,b4.z,b4.w};
            #pragma unroll
            for (int i=0;i<4;i++)
                #pragma unroll
                for (int j=0;j<4;j++) acc[i][j] += a_[i]*b_[j];
        }
        __syncthreads();
    }
    #pragma unroll
    for (int i=0;i<4;i++) {
        int m = m0 + ty*4 + i;
        #pragma unroll
        for (int j=0;j<4;j++) {
            int n = n0 + tx*4 + j;
            if (n < N) {
                float bb = acc[i][j];
                if (bias1) bb += bias1[n];
                if (bias2) bb += bias2[n];
                C[(size_t)m*N + n] = bb;
            }
        }
    }
}

// Persistent recurrence v3: 128 CTAs x 512 thr, flag-based producer/consumer sync.
// W_hh in registers (4 rows x 16 k per thread). Consumer thread c reads exactly
// producer-CTA c's 64-float chunk straight into registers (no SMEM broadcast,
// no global atomic barrier, no threadfence).
__global__ __launch_bounds__(512, 1) void recurrence_kernel(const float* __restrict__ Whh) {
    __shared__ float red[16 * 68];
    const int tid = threadIdx.x, cta = blockIdx.x;
    const int row0 = cta * ROWS_REC;
    const int g = tid & 3;           // row group (4 rows)
    const int c = tid >> 2;          // k-chunk index == producer CTA id (0..127)
    const int lane = tid & 31, warp = tid >> 5;

    // W slice -> registers: rows row0+g*4+i, k = c*16 + kq*4 .. +4
    ulonglong2 wr[4][4];
    #pragma unroll
    for (int i = 0; i < 4; i++) {
        const ulonglong2* p = (const ulonglong2*)(Whh + (size_t)(row0 + g*4 + i) * RES + c*16);
        #pragma unroll
        for (int kq = 0; kq < 4; kq++) wr[i][kq] = p[kq];
    }
    const int ob = tid & 3, orow = tid >> 2;   // output mapping for tid<64

    for (int t = 0; t < TLEN; t++) {
        float xv = 0.f;
        if (tid < 64) xv = g_xin[((size_t)(ob*TLEN + t))*RES + row0 + orow];

        float accs[4][4];
        if (t > 0) {
            // wait for my producer's chunk of h_t
            while (ld_acq(&g_flag[c]) < (unsigned)t) { }
            const ulonglong2* hp = (const ulonglong2*)g_h[t & 1][c];
            unsigned long long acc2[4][4];
            #pragma unroll
            for (int i = 0; i < 4; i++)
                #pragma unroll
                for (int j = 0; j < 4; j++) acc2[i][j] = 0ULL;
            #pragma unroll
            for (int b = 0; b < 4; b++) {
                #pragma unroll
                for (int kq = 0; kq < 4; kq++) {
                    ulonglong2 h2 = ldcg_u2(hp + b*4 + kq);
                    #pragma unroll
                    for (int i = 0; i < 4; i++) {
                        ffma2(acc2[i][b], wr[i][kq].x, h2.x);
                        ffma2(acc2[i][b], wr[i][kq].y, h2.y);
                    }
                }
            }
            #pragma unroll
            for (int i = 0; i < 4; i++)
                #pragma unroll
                for (int j = 0; j < 4; j++) {
                    float2 f = *reinterpret_cast<float2*>(&acc2[i][j]);
                    accs[i][j] = f.x + f.y;
                }
            // butterfly over c_local (lane bits 2..4)
            #pragma unroll
            for (int i = 0; i < 4; i++)
                #pragma unroll
                for (int j = 0; j < 4; j++) {
                    accs[i][j] += __shfl_xor_sync(0xffffffffu, accs[i][j], 4);
                    accs[i][j] += __shfl_xor_sync(0xffffffffu, accs[i][j], 8);
                    accs[i][j] += __shfl_xor_sync(0xffffffffu, accs[i][j], 16);
                }
        } else {
            #pragma unroll
            for (int i = 0; i < 4; i++)
                #pragma unroll
                for (int j = 0; j < 4; j++) accs[i][j] = 0.f;
        }
        if (lane < 4) {   // c_local==0, lane==g
            #pragma unroll
            for (int i = 0; i < 4; i++)
                #pragma unroll
                for (int j = 0; j < 4; j++)
                    red[warp*68 + lane*16 + i*4 + j] = accs[i][j];
        }
        __syncthreads();
        if (tid < 64) {
            float y = xv;
            #pragma unroll
            for (int w = 0; w < 16; w++) y += red[w*68 + orow*4 + ob];
            float hv = tanhf(y);
            g_states_bt[((size_t)(ob*TLEN + t))*RES + row0 + orow] = hv;
            g_h[(t+1) & 1][cta][ob*16 + orow] = hv;
        }
        __syncthreads();
        if (tid == 0) st_rel(&g_flag[cta], (unsigned)(t + 1));
    }
}

__global__ __launch_bounds__(256) void head_out_kernel(const int* __restrict__ targets,
                                                       float* __restrict__ out) {
    __shared__ float lp[NHEAD2];
    __shared__ float rmax[8], rsum[8];
    const int tok = blockIdx.x, tid = threadIdx.x;
    const int lane = tid & 31, warp = tid >> 5;
    const float* Lrow = g_L + (size_t)tok * NHEAD2;
    for (int h = 0; h < 2; h++) {
        float v = (tid < SQV) ? Lrow[h*SQV + tid] : -3.4e38f;
        float m = v;
        #pragma unroll
        for (int off=16; off; off>>=1) m = fmaxf(m, __shfl_xor_sync(0xffffffffu, m, off));
        if (lane == 0) rmax[warp] = m;
        __syncthreads();
        float mx = fmaxf(fmaxf(fmaxf(rmax[0],rmax[1]),fmaxf(rmax[2],rmax[3])),
                         fmaxf(fmaxf(rmax[4],rmax[5]),fmaxf(rmax[6],rmax[7])));
        float e = (tid < SQV) ? expf(v - mx) : 0.f;
        float s = e;
        #pragma unroll
        for (int off=16; off; off>>=1) s += __shfl_xor_sync(0xffffffffu, s, off);
        if (lane == 0) rsum[warp] = s;
        __syncthreads();
        float st = rsum[0]+rsum[1]+rsum[2]+rsum[3]+rsum[4]+rsum[5]+rsum[6]+rsum[7];
        float lse = mx + logf(st);
        if (tid < SQV) lp[h*SQV + tid] = v - lse;
        __syncthreads();
    }
    if (tid == 0) {
        int tg = targets[tok];
        if (tg != -1) {
            int r = tg / SQV, c0 = tg - r*SQV;
            atomicAdd(&g_loss_acc, -(lp[r] + lp[SQV + c0]));
            atomicAdd(&g_mask_cnt, 1);
        }
    }
    size_t base = (size_t)tok * VOCAB;
    for (int i = tid; i < VOCAB; i += 256) {
        int r = i / SQV, c0 = i - r*SQV;
        out[base + i] = lp[r] + lp[SQV + c0];
    }
}

__global__ void finalize_kernel(float* __restrict__ out, size_t out_sz) {
    int i = blockIdx.x * blockDim.x + threadIdx.x;
    size_t need = LOGITS_N + 1 + (size_t)BATCH*RES;
    if (out_sz < need) return;
    if (i == 0) {
        int cnt = g_mask_cnt; if (cnt < 1) cnt = 1;
        out[LOGITS_N] = g_loss_acc / (float)cnt;
    }
    if (i < BATCH*RES) {
        int b = i / RES, r = i - b*RES;
        out[LOGITS_N + 1 + i] = g_states_bt[((size_t)(b*TLEN + TLEN-1))*RES + r];
    }
}

extern "C" void kernel_launch(void* const* d_in, const int* in_sizes, int n_in,
                              void* d_out, int out_size) {
    const int*   idx     = (const int*)  d_in[0];
    const int*   targets = (const int*)  d_in[1];
    const float* wte     = (const float*)d_in[2];
    const float* W_in    = (const float*)d_in[3];
    const float* W_ih    = (const float*)d_in[4];
    const float* b_ih    = (const float*)d_in[5];
    const float* W_hh    = (const float*)d_in[6];
    const float* b_hh    = (const float*)d_in[7];
    const float* Wh1     = (const float*)d_in[8];
    const float* Wh2     = (const float*)d_in[9];
    float* out = (float*)d_out;

    prep_kernel<<<1024, 256>>>(Wh1, Wh2);
    gemm_nn_wc<<<dim3(RES/64, EMBED/64), 256>>>(W_ih, W_in);
    gemm_nt<<<dim3(NTOK/64, RES/64), 256>>>(0, wte, idx, b_ih, b_hh, RES, EMBED);
    recurrence_kernel<<<NCTA_REC, 512>>>(W_hh);
    gemm_nt<<<dim3(NTOK/64, (NHEAD2+63)/64), 256>>>(1, nullptr, nullptr, nullptr, nullptr, NHEAD2, RES);
    head_out_kernel<<<NTOK, 256>>>(targets, out);
    finalize_kernel<<<(BATCH*RES+256)/256 + 1, 256>>>(out, (size_t)out_size);
}

// round 10
// speedup vs baseline: 1.7792x; 1.7792x over previous
#include <cuda_runtime.h>
#include <cuda_bf16.h>
#include <math.h>

#define RES    2048
#define EMBED  256
#define TLEN   512
#define BATCH  4
#define NTOK   (BATCH*TLEN)
#define SQV    225
#define NHEAD2 450
#define VOCAB  50257
#define NCTA_REC 128
#define ROWS_REC 16

static const size_t LOGITS_N = (size_t)NTOK * VOCAB;

__device__ float    g_Wc[RES * EMBED];
__device__ float    g_xin[(size_t)NTOK * RES];
__device__ float    g_states_bt[(size_t)NTOK * RES];
__device__ float    g_L[(size_t)NTOK * NHEAD2];
__device__ float    g_Whcat[NHEAD2 * RES];
__device__ float    g_h[2][NCTA_REC][64];     // double-buffered h chunks [b*16+kloc]
__device__ unsigned g_flag[NCTA_REC];         // last step produced by each CTA
__device__ float    g_loss_acc;
__device__ int      g_mask_cnt;

__device__ __forceinline__ unsigned ld_acq(const unsigned* p) {
    unsigned v;
    asm volatile("ld.acquire.gpu.u32 %0, [%1];" : "=r"(v) : "l"(p) : "memory");
    return v;
}
__device__ __forceinline__ void st_rel(unsigned* p, unsigned v) {
    asm volatile("st.release.gpu.u32 [%0], %1;" :: "l"(p), "r"(v) : "memory");
}
__device__ __forceinline__ ulonglong2 ldcg_u2(const ulonglong2* p) {
    ulonglong2 v;
    asm volatile("ld.global.cg.v2.u64 {%0,%1}, [%2];" : "=l"(v.x), "=l"(v.y) : "l"(p));
    return v;
}
// packed dual-FMA: d(f32x2) += a(f32x2) * b(f32x2)
__device__ __forceinline__ void ffma2(unsigned long long& d,
                                      unsigned long long a,
                                      unsigned long long b) {
    asm("fma.rn.f32x2 %0, %1, %2, %0;" : "+l"(d) : "l"(a), "l"(b));
}

__global__ void prep_kernel(const float* __restrict__ Wh1, const float* __restrict__ Wh2) {
    int i0 = blockIdx.x * blockDim.x + threadIdx.x;
    int stride = gridDim.x * blockDim.x;
    for (int j = i0; j < NHEAD2 * RES; j += stride) {
        int v = j / RES, r = j - v * RES;
        g_Whcat[j] = (v < SQV) ? Wh1[v * RES + r] : Wh2[(v - SQV) * RES + r];
    }
    if (i0 < NCTA_REC) g_flag[i0] = 0u;
    if (i0 == 0) { g_loss_acc = 0.f; g_mask_cnt = 0; }
}

// Wc = W_ih[2048x2048] @ W_in[2048x256]   (NN GEMM)
__global__ __launch_bounds__(256) void gemm_nn_wc(const float* __restrict__ A,
                                                  const float* __restrict__ B) {
    const int N = EMBED, K = RES;
    __shared__ float As[16][68];
    __shared__ float Bs[16][68];
    int m0 = blockIdx.x * 64, n0 = blockIdx.y * 64;
    int tid = threadIdx.x;
    int lr = tid >> 2, lk = tid & 3;
    const float* Arow = A + (size_t)(m0 + lr) * K + lk * 4;
    int bk = tid >> 4, bn = tid & 15;
    const float* Bpos = B + (size_t)bk * N + n0 + bn * 4;
    int tx = tid & 15, ty = tid >> 4;
    float acc[4][4] = {};
    float4 av = *(const float4*)(Arow);
    float4 bv = *(const float4*)(Bpos);
    for (int k0 = 0; k0 < K; k0 += 16) {
        As[lk*4+0][lr]=av.x; As[lk*4+1][lr]=av.y; As[lk*4+2][lr]=av.z; As[lk*4+3][lr]=av.w;
        *(float4*)&Bs[bk][bn*4] = bv;
        __syncthreads();
        if (k0 + 16 < K) {
            av = *(const float4*)(Arow + k0 + 16);
            bv = *(const float4*)(Bpos + (size_t)(k0 + 16) * N);
        }
        #pragma unroll
        for (int kk = 0; kk < 16; kk++) {
            float4 a4 = *(const float4*)&As[kk][ty*4];
            float4 b4 = *(const float4*)&Bs[kk][tx*4];
            float a_[4]={a4.x,a4.y,a4.z,a4.w}, b_[4]={b4.x,b4.y,b4.z,b4.w};
            #pragma unroll
            for (int i=0;i<4;i++)
                #pragma unroll
                for (int j=0;j<4;j++) acc[i][j] += a_[i]*b_[j];
        }
        __syncthreads();
    }
    #pragma unroll
    for (int i=0;i<4;i++) {
        int m = m0 + ty*4 + i;
        #pragma unroll
        for (int j=0;j<4;j++) g_Wc[(size_t)m*N + n0 + tx*4 + j] = acc[i][j];
    }
}

// NT GEMM. mode 0: g_xin = wte[idx] @ Wc^T + b_ih + b_hh   (M=2048,N=2048,K=256)
//          mode 1: g_L   = g_states_bt @ g_Whcat^T          (M=2048,N=450, K=2048)
__global__ __launch_bounds__(256) void gemm_nt(int mode, const float* __restrict__ Aext,
                                               const int* __restrict__ gather,
                                               const float* __restrict__ bias1,
                                               const float* __restrict__ bias2,
                                               int N, int K) {
    const float *A, *B; float* C;
    if (mode == 0) { A = Aext;        B = g_Wc;    C = g_xin; }
    else           { A = g_states_bt; B = g_Whcat; C = g_L;   }
    __shared__ float As[16][68];
    __shared__ float Bs[16][68];
    int m0 = blockIdx.x * 64, n0 = blockIdx.y * 64;
    int tid = threadIdx.x;
    int lr = tid >> 2, lk = tid & 3;
    int am = m0 + lr;
    int arow = gather ? gather[am] : am;
    const float* Arow = A + (size_t)arow * K + lk * 4;
    int bn = n0 + lr;
    bool bvalid = (bn < N);
    const float* Brow = B + (size_t)(bvalid ? bn : 0) * K + lk * 4;
    int tx = tid & 15, ty = tid >> 4;
    float acc[4][4] = {};
    float4 av = *(const float4*)(Arow);
    float4 bv = bvalid ? *(const float4*)(Brow) : make_float4(0,0,0,0);
    for (int k0 = 0; k0 < K; k0 += 16) {
        As[lk*4+0][lr]=av.x; As[lk*4+1][lr]=av.y; As[lk*4+2][lr]=av.z; As[lk*4+3][lr]=av.w;
        Bs[lk*4+0][lr]=bv.x; Bs[lk*4+1][lr]=bv.y; Bs[lk*4+2][lr]=bv.z; Bs[lk*4+3][lr]=bv.w;
        __syncthreads();
        if (k0 + 16 < K) {
            av = *(const float4*)(Arow + k0 + 16);
            bv = bvalid ? *(const float4*)(Brow + k0 + 16) : make_float4(0,0,0,0);
        }
        #pragma unroll
        for (int kk = 0; kk < 16; kk++) {
            float4 a4 = *(const float4*)&As[kk][ty*4];
            float4 b4 = *(const float4*)&Bs[kk][tx*4];
            float a_[4]={a4.x,a4.y,a4.z,a4.w}, b_[4]={b4.x,b4.y,b4.z,b4.w};
            #pragma unroll
            for (int i=0;i<4;i++)
                #pragma unroll
                for (int j=0;j<4;j++) acc[i][j] += a_[i]*b_[j];
        }
        __syncthreads();
    }
    #pragma unroll
    for (int i=0;i<4;i++) {
        int m = m0 + ty*4 + i;
        #pragma unroll
        for (int j=0;j<4;j++) {
            int n = n0 + tx*4 + j;
            if (n < N) {
                float bb = acc[i][j];
                if (bias1) bb += bias1[n];
                if (bias2) bb += bias2[n];
                C[(size_t)m*N + n] = bb;
            }
        }
    }
}

// Persistent recurrence v4: 128 CTAs x 512 thr.
// W_hh in registers; h chunks consumed straight into registers (coalescer
// dedups the 4-lane shared addresses). Sync: ONE warp polls the 128 flags
// (each lane acquires 4), everyone else parks on __syncthreads. No atomics.
__global__ __launch_bounds__(512, 1) void recurrence_kernel(const float* __restrict__ Whh) {
    __shared__ float red[16 * 68];
    const int tid = threadIdx.x, cta = blockIdx.x;
    const int row0 = cta * ROWS_REC;
    const int g = tid & 3;           // row group (4 rows)
    const int c = tid >> 2;          // k-chunk index == producer CTA id (0..127)
    const int lane = tid & 31, warp = tid >> 5;

    // W slice -> registers: rows row0+g*4+i, k = c*16 + kq*4 .. +4
    ulonglong2 wr[4][4];
    #pragma unroll
    for (int i = 0; i < 4; i++) {
        const ulonglong2* p = (const ulonglong2*)(Whh + (size_t)(row0 + g*4 + i) * RES + c*16);
        #pragma unroll
        for (int kq = 0; kq < 4; kq++) wr[i][kq] = p[kq];
    }
    const int ob = tid & 3, orow = tid >> 2;   // output mapping for tid<64

    for (int t = 0; t < TLEN; t++) {
        float xv = 0.f;
        if (tid < 64) xv = g_xin[((size_t)(ob*TLEN + t))*RES + row0 + orow];

        float accs[4][4];
        if (t > 0) {
            // warp 0 waits for ALL producers' chunks of h_t; rest park at barrier
            if (warp == 0) {
                const unsigned* fp = g_flag + lane * 4;
                for (;;) {
                    unsigned f0 = ld_acq(fp+0), f1 = ld_acq(fp+1);
                    unsigned f2 = ld_acq(fp+2), f3 = ld_acq(fp+3);
                    unsigned mn = min(min(f0,f1), min(f2,f3));
                    if (__all_sync(0xffffffffu, mn >= (unsigned)t)) break;
                }
            }
            __syncthreads();

            const ulonglong2* hp = (const ulonglong2*)g_h[t & 1][c];
            unsigned long long acc2[4][4];
            #pragma unroll
            for (int i = 0; i < 4; i++)
                #pragma unroll
                for (int j = 0; j < 4; j++) acc2[i][j] = 0ULL;
            #pragma unroll
            for (int b = 0; b < 4; b++) {
                #pragma unroll
                for (int kq = 0; kq < 4; kq++) {
                    ulonglong2 h2 = ldcg_u2(hp + b*4 + kq);
                    #pragma unroll
                    for (int i = 0; i < 4; i++) {
                        ffma2(acc2[i][b], wr[i][kq].x, h2.x);
                        ffma2(acc2[i][b], wr[i][kq].y, h2.y);
                    }
                }
            }
            #pragma unroll
            for (int i = 0; i < 4; i++)
                #pragma unroll
                for (int j = 0; j < 4; j++) {
                    float2 f = *reinterpret_cast<float2*>(&acc2[i][j]);
                    accs[i][j] = f.x + f.y;
                }
            // butterfly over c_local (lane bits 2..4)
            #pragma unroll
            for (int i = 0; i < 4; i++)
                #pragma unroll
                for (int j = 0; j < 4; j++) {
                    accs[i][j] += __shfl_xor_sync(0xffffffffu, accs[i][j], 4);
                    accs[i][j] += __shfl_xor_sync(0xffffffffu, accs[i][j], 8);
                    accs[i][j] += __shfl_xor_sync(0xffffffffu, accs[i][j], 16);
                }
        } else {
            #pragma unroll
            for (int i = 0; i < 4; i++)
                #pragma unroll
                for (int j = 0; j < 4; j++) accs[i][j] = 0.f;
        }
        if (lane < 4) {   // c_local==0, lane==g
            #pragma unroll
            for (int i = 0; i < 4; i++)
                #pragma unroll
                for (int j = 0; j < 4; j++)
                    red[warp*68 + lane*16 + i*4 + j] = accs[i][j];
        }
        __syncthreads();
        if (tid < 64) {
            float y = xv;
            #pragma unroll
            for (int w = 0; w < 16; w++) y += red[w*68 + orow*4 + ob];
            float hv = tanhf(y);
            g_states_bt[((size_t)(ob*TLEN + t))*RES + row0 + orow] = hv;
            g_h[(t+1) & 1][cta][ob*16 + orow] = hv;
        }
        __syncthreads();
        if (tid == 0) st_rel(&g_flag[cta], (unsigned)(t + 1));
    }
}

__global__ __launch_bounds__(256) void head_out_kernel(const int* __restrict__ targets,
                                                       float* __restrict__ out) {
    __shared__ float lp[NHEAD2];
    __shared__ float rmax[8], rsum[8];
    const int tok = blockIdx.x, tid = threadIdx.x;
    const int lane = tid & 31, warp = tid >> 5;
    const float* Lrow = g_L + (size_t)tok * NHEAD2;
    for (int h = 0; h < 2; h++) {
        float v = (tid < SQV) ? Lrow[h*SQV + tid] : -3.4e38f;
        float m = v;
        #pragma unroll
        for (int off=16; off; off>>=1) m = fmaxf(m, __shfl_xor_sync(0xffffffffu, m, off));
        if (lane == 0) rmax[warp] = m;
        __syncthreads();
        float mx = fmaxf(fmaxf(fmaxf(rmax[0],rmax[1]),fmaxf(rmax[2],rmax[3])),
                         fmaxf(fmaxf(rmax[4],rmax[5]),fmaxf(rmax[6],rmax[7])));
        float e = (tid < SQV) ? expf(v - mx) : 0.f;
        float s = e;
        #pragma unroll
        for (int off=16; off; off>>=1) s += __shfl_xor_sync(0xffffffffu, s, off);
        if (lane == 0) rsum[warp] = s;
        __syncthreads();
        float st = rsum[0]+rsum[1]+rsum[2]+rsum[3]+rsum[4]+rsum[5]+rsum[6]+rsum[7];
        float lse = mx + logf(st);
        if (tid < SQV) lp[h*SQV + tid] = v - lse;
        __syncthreads();
    }
    if (tid == 0) {
        int tg = targets[tok];
        if (tg != -1) {
            int r = tg / SQV, c0 = tg - r*SQV;
            atomicAdd(&g_loss_acc, -(lp[r] + lp[SQV + c0]));
            atomicAdd(&g_mask_cnt, 1);
        }
    }
    size_t base = (size_t)tok * VOCAB;
    for (int i = tid; i < VOCAB; i += 256) {
        int r = i / SQV, c0 = i - r*SQV;
        out[base + i] = lp[r] + lp[SQV + c0];
    }
}

__global__ void finalize_kernel(float* __restrict__ out, size_t out_sz) {
    int i = blockIdx.x * blockDim.x + threadIdx.x;
    size_t need = LOGITS_N + 1 + (size_t)BATCH*RES;
    if (out_sz < need) return;
    if (i == 0) {
        int cnt = g_mask_cnt; if (cnt < 1) cnt = 1;
        out[LOGITS_N] = g_loss_acc / (float)cnt;
    }
    if (i < BATCH*RES) {
        int b = i / RES, r = i - b*RES;
        out[LOGITS_N + 1 + i] = g_states_bt[((size_t)(b*TLEN + TLEN-1))*RES + r];
    }
}

extern "C" void kernel_launch(void* const* d_in, const int* in_sizes, int n_in,
                              void* d_out, int out_size) {
    const int*   idx     = (const int*)  d_in[0];
    const int*   targets = (const int*)  d_in[1];
    const float* wte     = (const float*)d_in[2];
    const float* W_in    = (const float*)d_in[3];
    const float* W_ih    = (const float*)d_in[4];
    const float* b_ih    = (const float*)d_in[5];
    const float* W_hh    = (const float*)d_in[6];
    const float* b_hh    = (const float*)d_in[7];
    const float* Wh1     = (const float*)d_in[8];
    const float* Wh2     = (const float*)d_in[9];
    float* out = (float*)d_out;

    prep_kernel<<<1024, 256>>>(Wh1, Wh2);
    gemm_nn_wc<<<dim3(RES/64, EMBED/64), 256>>>(W_ih, W_in);
    gemm_nt<<<dim3(NTOK/64, RES/64), 256>>>(0, wte, idx, b_ih, b_hh, RES, EMBED);
    recurrence_kernel<<<NCTA_REC, 512>>>(W_hh);
    gemm_nt<<<dim3(NTOK/64, (NHEAD2+63)/64), 256>>>(1, nullptr, nullptr, nullptr, nullptr, NHEAD2, RES);
    head_out_kernel<<<NTOK, 256>>>(targets, out);
    finalize_kernel<<<(BATCH*RES+256)/256 + 1, 256>>>(out, (size_t)out_size);
}

// round 17
// speedup vs baseline: 3.6733x; 2.0645x over previous
#include <cuda_runtime.h>
#include <cuda_bf16.h>
#include <math.h>

#define RES    2048
#define EMBED  256
#define TLEN   512
#define BATCH  4
#define NTOK   (BATCH*TLEN)
#define SQV    225
#define NHEAD2 450
#define VOCAB  50257
#define NCTA_REC 128
#define ROWS_REC 16
#define FLAG_STRIDE 32   // pad each flag to its own 128B line

static const size_t LOGITS_N = (size_t)NTOK * VOCAB;

__device__ float    g_Wc[RES * EMBED];
__device__ float    g_xin[(size_t)NTOK * RES];
__device__ float    g_states_bt[(size_t)NTOK * RES];
__device__ float    g_L[(size_t)NTOK * NHEAD2];
__device__ float    g_Whcat[NHEAD2 * RES];
__device__ float    g_h[2][NCTA_REC][64];            // double-buffered h chunks [b*16+kloc]
__device__ unsigned g_flag[NCTA_REC * FLAG_STRIDE];  // one 128B line per producer CTA
__device__ float    g_loss_acc;
__device__ int      g_mask_cnt;

__device__ __forceinline__ unsigned ld_acq(const unsigned* p) {
    unsigned v;
    asm volatile("ld.acquire.gpu.u32 %0, [%1];" : "=r"(v) : "l"(p) : "memory");
    return v;
}
__device__ __forceinline__ void st_rel(unsigned* p, unsigned v) {
    asm volatile("st.release.gpu.u32 [%0], %1;" :: "l"(p), "r"(v) : "memory");
}
__device__ __forceinline__ ulonglong2 ldcg_u2(const ulonglong2* p) {
    ulonglong2 v;
    asm volatile("ld.global.cg.v2.u64 {%0,%1}, [%2];" : "=l"(v.x), "=l"(v.y) : "l"(p));
    return v;
}
// packed dual-FMA: d(f32x2) += a(f32x2) * b(f32x2)
__device__ __forceinline__ void ffma2(unsigned long long& d,
                                      unsigned long long a,
                                      unsigned long long b) {
    asm("fma.rn.f32x2 %0, %1, %2, %0;" : "+l"(d) : "l"(a), "l"(b));
}

__global__ void prep_kernel(const float* __restrict__ Wh1, const float* __restrict__ Wh2) {
    int i0 = blockIdx.x * blockDim.x + threadIdx.x;
    int stride = gridDim.x * blockDim.x;
    for (int j = i0; j < NHEAD2 * RES; j += stride) {
        int v = j / RES, r = j - v * RES;
        g_Whcat[j] = (v < SQV) ? Wh1[v * RES + r] : Wh2[(v - SQV) * RES + r];
    }
    for (int j = i0; j < NCTA_REC * FLAG_STRIDE; j += stride) g_flag[j] = 0u;
    if (i0 == 0) { g_loss_acc = 0.f; g_mask_cnt = 0; }
}

// Wc = W_ih[2048x2048] @ W_in[2048x256]   (NN GEMM)
__global__ __launch_bounds__(256) void gemm_nn_wc(const float* __restrict__ A,
                                                  const float* __restrict__ B) {
    const int N = EMBED, K = RES;
    __shared__ float As[16][68];
    __shared__ float Bs[16][68];
    int m0 = blockIdx.x * 64, n0 = blockIdx.y * 64;
    int tid = threadIdx.x;
    int lr = tid >> 2, lk = tid & 3;
    const float* Arow = A + (size_t)(m0 + lr) * K + lk * 4;
    int bk = tid >> 4, bn = tid & 15;
    const float* Bpos = B + (size_t)bk * N + n0 + bn * 4;
    int tx = tid & 15, ty = tid >> 4;
    float acc[4][4] = {};
    float4 av = *(const float4*)(Arow);
    float4 bv = *(const float4*)(Bpos);
    for (int k0 = 0; k0 < K; k0 += 16) {
        As[lk*4+0][lr]=av.x; As[lk*4+1][lr]=av.y; As[lk*4+2][lr]=av.z; As[lk*4+3][lr]=av.w;
        *(float4*)&Bs[bk][bn*4] = bv;
        __syncthreads();
        if (k0 + 16 < K) {
            av = *(const float4*)(Arow + k0 + 16);
            bv = *(const float4*)(Bpos + (size_t)(k0 + 16) * N);
        }
        #pragma unroll
        for (int kk = 0; kk < 16; kk++) {
            float4 a4 = *(const float4*)&As[kk][ty*4];
            float4 b4 = *(const float4*)&Bs[kk][tx*4];
            float a_[4]={a4.x,a4.y,a4.z,a4.w}, b_[4]={b4.x,b4.y,b4.z,b4.w};
            #pragma unroll
            for (int i=0;i<4;i++)
                #pragma unroll
                for (int j=0;j<4;j++) acc[i][j] += a_[i]*b_[j];
        }
        __syncthreads();
    }
    #pragma unroll
    for (int i=0;i<4;i++) {
        int m = m0 + ty*4 + i;
        #pragma unroll
        for (int j=0;j<4;j++) g_Wc[(size_t)m*N + n0 + tx*4 + j] = acc[i][j];
    }
}

// NT GEMM. mode 0: g_xin = wte[idx] @ Wc^T + b_ih + b_hh   (M=2048,N=2048,K=256)
//          mode 1: g_L   = g_states_bt @ g_Whcat^T          (M=2048,N=450, K=2048)
__global__ __launch_bounds__(256) void gemm_nt(int mode, const float* __restrict__ Aext,
                                               const int* __restrict__ gather,
                                               const float* __restrict__ bias1,
                                               const float* __restrict__ bias2,
                                               int N, int K) {
    const float *A, *B; float* C;
    if (mode == 0) { A = Aext;        B = g_Wc;    C = g_xin; }
    else           { A = g_states_bt; B = g_Whcat; C = g_L;   }
    __shared__ float As[16][68];
    __shared__ float Bs[16][68];
    int m0 = blockIdx.x * 64, n0 = blockIdx.y * 64;
    int tid = threadIdx.x;
    int lr = tid >> 2, lk = tid & 3;
    int am = m0 + lr;
    int arow = gather ? gather[am] : am;
    const float* Arow = A + (size_t)arow * K + lk * 4;
    int bn = n0 + lr;
    bool bvalid = (bn < N);
    const float* Brow = B + (size_t)(bvalid ? bn : 0) * K + lk * 4;
    int tx = tid & 15, ty = tid >> 4;
    float acc[4][4] = {};
    float4 av = *(const float4*)(Arow);
    float4 bv = bvalid ? *(const float4*)(Brow) : make_float4(0,0,0,0);
    for (int k0 = 0; k0 < K; k0 += 16) {
        As[lk*4+0][lr]=av.x; As[lk*4+1][lr]=av.y; As[lk*4+2][lr]=av.z; As[lk*4+3][lr]=av.w;
        Bs[lk*4+0][lr]=bv.x; Bs[lk*4+1][lr]=bv.y; Bs[lk*4+2][lr]=bv.z; Bs[lk*4+3][lr]=bv.w;
        __syncthreads();
        if (k0 + 16 < K) {
            av = *(const float4*)(Arow + k0 + 16);
            bv = bvalid ? *(const float4*)(Brow + k0 + 16) : make_float4(0,0,0,0);
        }
        #pragma unroll
        for (int kk = 0; kk < 16; kk++) {
            float4 a4 = *(const float4*)&As[kk][ty*4];
            float4 b4 = *(const float4*)&Bs[kk][tx*4];
            float a_[4]={a4.x,a4.y,a4.z,a4.w}, b_[4]={b4.x,b4.y,b4.z,b4.w};
            #pragma unroll
            for (int i=0;i<4;i++)
                #pragma unroll
                for (int j=0;j<4;j++) acc[i][j] += a_[i]*b_[j];
        }
        __syncthreads();
    }
    #pragma unroll
    for (int i=0;i<4;i++) {
        int m = m0 + ty*4 + i;
        #pragma unroll
        for (int j=0;j<4;j++) {
            int n = n0 + tx*4 + j;
            if (n < N) {
                float bb = acc[i][j];
                if (bias1) bb += bias1[n];
                if (bias2) bb += bias2[n];
                C[(size_t)m*N + n] = bb;
            }
        }
    }
}

// Persistent recurrence v6: 128 CTAs x 512 thr.
// W_hh in registers; h chunks consumed straight into registers. Sync: flags
// padded to one 128B line each; threads 0..127 poll ONE flag each with a
// single ld.acquire.gpu per iteration (no acquire chains; slices spread);
// warps 4..15 park at __syncthreads. Producer: st.release per own line.
// (v5's relaxed .cg poll was formally racy and measured wrong: rel_err 5.8e-2.
//  R10's acquire discipline passed at 1.5e-6 — acquire is required.)
__global__ __launch_bounds__(512, 1) void recurrence_kernel(const float* __restrict__ Whh) {
    __shared__ float red[16 * 68];
    const int tid = threadIdx.x, cta = blockIdx.x;
    const int row0 = cta * ROWS_REC;
    const int g = tid & 3;           // row group (4 rows)
    const int c = tid >> 2;          // k-chunk index == producer CTA id (0..127)
    const int lane = tid & 31, warp = tid >> 5;

    // W slice -> registers: rows row0+g*4+i, k = c*16 + kq*4 .. +4
    ulonglong2 wr[4][4];
    #pragma unroll
    for (int i = 0; i < 4; i++) {
        const ulonglong2* p = (const ulonglong2*)(Whh + (size_t)(row0 + g*4 + i) * RES + c*16);
        #pragma unroll
        for (int kq = 0; kq < 4; kq++) wr[i][kq] = p[kq];
    }
    const int ob = tid & 3, orow = tid >> 2;   // output mapping for tid<64
    const unsigned* myflag = g_flag + tid * FLAG_STRIDE;   // valid for tid<128

    for (int t = 0; t < TLEN; t++) {
        float xv = 0.f;
        if (tid < 64) xv = g_xin[((size_t)(ob*TLEN + t))*RES + row0 + orow];

        float accs[4][4];
        if (t > 0) {
            // threads 0..127 each poll exactly one padded flag (acquire); others park
            if (tid < NCTA_REC) {
                while (ld_acq(myflag) < (unsigned)t) { }
            }
            __syncthreads();

            const ulonglong2* hp = (const ulonglong2*)g_h[t & 1][c];
            unsigned long long acc2[4][4];
            #pragma unroll
            for (int i = 0; i < 4; i++)
                #pragma unroll
                for (int j = 0; j < 4; j++) acc2[i][j] = 0ULL;
            #pragma unroll
            for (int b = 0; b < 4; b++) {
                #pragma unroll
                for (int kq = 0; kq < 4; kq++) {
                    ulonglong2 h2 = ldcg_u2(hp + b*4 + kq);
                    #pragma unroll
                    for (int i = 0; i < 4; i++) {
                        ffma2(acc2[i][b], wr[i][kq].x, h2.x);
                        ffma2(acc2[i][b], wr[i][kq].y, h2.y);
                    }
                }
            }
            #pragma unroll
            for (int i = 0; i < 4; i++)
                #pragma unroll
                for (int j = 0; j < 4; j++) {
                    float2 f = *reinterpret_cast<float2*>(&acc2[i][j]);
                    accs[i][j] = f.x + f.y;
                }
            // butterfly over c_local (lane bits 2..4)
            #pragma unroll
            for (int i = 0; i < 4; i++)
                #pragma unroll
                for (int j = 0; j < 4; j++) {
                    accs[i][j] += __shfl_xor_sync(0xffffffffu, accs[i][j], 4);
                    accs[i][j] += __shfl_xor_sync(0xffffffffu, accs[i][j], 8);
                    accs[i][j] += __shfl_xor_sync(0xffffffffu, accs[i][j], 16);
                }
        } else {
            #pragma unroll
            for (int i = 0; i < 4; i++)
                #pragma unroll
                for (int j = 0; j < 4; j++) accs[i][j] = 0.f;
        }
        if (lane < 4) {   // c_local==0, lane==g
            #pragma unroll
            for (int i = 0; i < 4; i++)
                #pragma unroll
                for (int j = 0; j < 4; j++)
                    red[warp*68 + lane*16 + i*4 + j] = accs[i][j];
        }
        __syncthreads();
        if (tid < 64) {
            float y = xv;
            #pragma unroll
            for (int w = 0; w < 16; w++) y += red[w*68 + orow*4 + ob];
            float hv = tanhf(y);
            g_states_bt[((size_t)(ob*TLEN + t))*RES + row0 + orow] = hv;
            g_h[(t+1) & 1][cta][ob*16 + orow] = hv;
        }
        __syncthreads();
        if (tid == 0) st_rel(&g_flag[cta * FLAG_STRIDE], (unsigned)(t + 1));
    }
}

__global__ __launch_bounds__(256) void head_out_kernel(const int* __restrict__ targets,
                                                       float* __restrict__ out) {
    __shared__ float lp[NHEAD2];
    __shared__ float rmax[8], rsum[8];
    const int tok = blockIdx.x, tid = threadIdx.x;
    const int lane = tid & 31, warp = tid >> 5;
    const float* Lrow = g_L + (size_t)tok * NHEAD2;
    for (int h = 0; h < 2; h++) {
        float v = (tid < SQV) ? Lrow[h*SQV + tid] : -3.4e38f;
        float m = v;
        #pragma unroll
        for (int off=16; off; off>>=1) m = fmaxf(m, __shfl_xor_sync(0xffffffffu, m, off));
        if (lane == 0) rmax[warp] = m;
        __syncthreads();
        float mx = fmaxf(fmaxf(fmaxf(rmax[0],rmax[1]),fmaxf(rmax[2],rmax[3])),
                         fmaxf(fmaxf(rmax[4],rmax[5]),fmaxf(rmax[6],rmax[7])));
        float e = (tid < SQV) ? expf(v - mx) : 0.f;
        float s = e;
        #pragma unroll
        for (int off=16; off; off>>=1) s += __shfl_xor_sync(0xffffffffu, s, off);
        if (lane == 0) rsum[warp] = s;
        __syncthreads();
        float st = rsum[0]+rsum[1]+rsum[2]+rsum[3]+rsum[4]+rsum[5]+rsum[6]+rsum[7];
        float lse = mx + logf(st);
        if (tid < SQV) lp[h*SQV + tid] = v - lse;
        __syncthreads();
    }
    if (tid == 0) {
        int tg = targets[tok];
        if (tg != -1) {
            int r = tg / SQV, c0 = tg - r*SQV;
            atomicAdd(&g_loss_acc, -(lp[r] + lp[SQV + c0]));
            atomicAdd(&g_mask_cnt, 1);
        }
    }
    size_t base = (size_t)tok * VOCAB;
    for (int i = tid; i < VOCAB; i += 256) {
        int r = i / SQV, c0 = i - r*SQV;
        out[base + i] = lp[r] + lp[SQV + c0];
    }
}

__global__ void finalize_kernel(float* __restrict__ out, size_t out_sz) {
    int i = blockIdx.x * blockDim.x + threadIdx.x;
    size_t need = LOGITS_N + 1 + (size_t)BATCH*RES;
    if (out_sz < need) return;
    if (i == 0) {
        int cnt = g_mask_cnt; if (cnt < 1) cnt = 1;
        out[LOGITS_N] = g_loss_acc / (float)cnt;
    }
    if (i < BATCH*RES) {
        int b = i / RES, r = i - b*RES;
        out[LOGITS_N + 1 + i] = g_states_bt[((size_t)(b*TLEN + TLEN-1))*RES + r];
    }
}

extern "C" void kernel_launch(void* const* d_in, const int* in_sizes, int n_in,
                              void* d_out, int out_size) {
    const int*   idx     = (const int*)  d_in[0];
    const int*   targets = (const int*)  d_in[1];
    const float* wte     = (const float*)d_in[2];
    const float* W_in    = (const float*)d_in[3];
    const float* W_ih    = (const float*)d_in[4];
    const float* b_ih    = (const float*)d_in[5];
    const float* W_hh    = (const float*)d_in[6];
    const float* b_hh    = (const float*)d_in[7];
    const float* Wh1     = (const float*)d_in[8];
    const float* Wh2     = (const float*)d_in[9];
    float* out = (float*)d_out;

    prep_kernel<<<1024, 256>>>(Wh1, Wh2);
    gemm_nn_wc<<<dim3(RES/64, EMBED/64), 256>>>(W_ih, W_in);
    gemm_nt<<<dim3(NTOK/64, RES/64), 256>>>(0, wte, idx, b_ih, b_hh, RES, EMBED);
    recurrence_kernel<<<NCTA_REC, 512>>>(W_hh);
    gemm_nt<<<dim3(NTOK/64, (NHEAD2+63)/64), 256>>>(1, nullptr, nullptr, nullptr, nullptr, NHEAD2, RES);
    head_out_kernel<<<NTOK, 256>>>(targets, out);
    finalize_kernel<<<(BATCH*RES+256)/256 + 1, 256>>>(out, (size_t)out_size);
}